// round 13
// baseline (speedup 1.0000x reference)
#include <cuda_runtime.h>
#include <cuda_bf16.h>
#include <math.h>

// Problem dims
#define B_  128
#define R_  1152
#define C_  10
#define O_  16
#define I_  338
#define N_  160
#define BRS (R_*N_)
#define NCHUNK 16
#define RCHUNK (R_/NCHUNK)    // 72

#define KC 16                 // k per stage
#define NSTAGES 22            // ceil(338/16)
#define NH 80                 // N per block

// Scratch
__device__ float g_uhat[(size_t)B_ * R_ * N_];
__device__ float g_b[R_ * C_];
__device__ float g_c[R_ * C_];
__device__ float g_v[B_ * N_];
__device__ float g_spart[NCHUNK * B_ * N_];

// ---------------------------------------------------------------------------
__device__ __forceinline__ unsigned sptr(const void* p) {
    return (unsigned)__cvta_generic_to_shared(p);
}
__device__ __forceinline__ void ldsm4(unsigned* d, unsigned a) {
    asm volatile("ldmatrix.sync.aligned.m8n8.x4.shared.b16 {%0,%1,%2,%3}, [%4];"
                 : "=r"(d[0]), "=r"(d[1]), "=r"(d[2]), "=r"(d[3]) : "r"(a));
}
__device__ __forceinline__ void ldsm2(unsigned* d, unsigned a) {
    asm volatile("ldmatrix.sync.aligned.m8n8.x2.shared.b16 {%0,%1}, [%2];"
                 : "=r"(d[0]), "=r"(d[1]) : "r"(a));
}
__device__ __forceinline__ void mma16816(float* c, const unsigned* a, const unsigned* b) {
    asm volatile(
        "mma.sync.aligned.m16n8k16.row.col.f32.bf16.bf16.f32 "
        "{%0,%1,%2,%3}, {%4,%5,%6,%7}, {%8,%9}, {%0,%1,%2,%3};"
        : "+f"(c[0]), "+f"(c[1]), "+f"(c[2]), "+f"(c[3])
        : "r"(a[0]), "r"(a[1]), "r"(a[2]), "r"(a[3]), "r"(b[0]), "r"(b[1]));
}
__device__ __forceinline__ unsigned pack_hi(float a, float b) {
    __nv_bfloat162 h = __halves2bfloat162(__float2bfloat16(a), __float2bfloat16(b));
    return *reinterpret_cast<unsigned*>(&h);
}
__device__ __forceinline__ unsigned pack_lo(float a, float b) {
    float ha = __bfloat162float(__float2bfloat16(a));
    float hb = __bfloat162float(__float2bfloat16(b));
    __nv_bfloat162 l = __halves2bfloat162(__float2bfloat16(a - ha),
                                          __float2bfloat16(b - hb));
    return *reinterpret_cast<unsigned*>(&l);
}
__device__ __forceinline__ void sts128(void* p, unsigned a, unsigned b,
                                       unsigned c, unsigned d) {
    asm volatile("st.shared.v4.u32 [%0], {%1, %2, %3, %4};"
                 :: "r"(sptr(p)), "r"(a), "r"(b), "r"(c), "r"(d) : "memory");
}
// swizzled byte offset in a compact 32B-row tile: row m, k-half kh (0/1).
// bank-group (m*8 + s*4) mod 32 is a permutation for both the STS pattern
// (m = t>>1, kh = t&1) and the ldsm pattern (8 consecutive m, fixed kh).
__device__ __forceinline__ int swz(int m, int kh) {
    return m * 32 + ((kh ^ ((m >> 2) & 1)) << 4);
}

// ---------------------------------------------------------------------------
__global__ void init_kernel() {
    int i = blockIdx.x * blockDim.x + threadIdx.x;
    if (i < R_ * C_) {
        g_b[i] = 0.0f;
        g_c[i] = 1.0f / (float)R_;   // softmax of zero logits over routes
    }
}

// ---------------------------------------------------------------------------
// u_hat via bf16 hi/lo split HMMA, pipelined, double-buffered smem.
// Staging: LDG.64 (8B-aligned safe for both x and W) + swizzled STS.128.
// grid (2, R_): both nhalf CTAs of a route co-resident -> x L2 reuse.
__global__ __launch_bounds__(256, 2) void uhat_kernel(const float* __restrict__ x,
                                                      const float* __restrict__ W) {
    const int nhalf = blockIdx.x;
    const int r     = blockIdx.y;
    const int t     = threadIdx.x;
    const int warp  = t >> 5;
    const int lane  = t & 31;
    const int wm    = warp >> 1;
    const int wn    = warp & 1;

    // compact 32B rows, double buffered: A 4096B/plane, W 2560B/plane
    __shared__ char a_hi[2][4096], a_lo[2][4096];
    __shared__ char b_hi[2][2560], b_lo[2][2560];

    const float* xr = x + (size_t)r * I_;
    const float* wr = W + (size_t)r * N_ * I_ + (size_t)nhalf * NH * I_;
    const size_t XS = (size_t)R_ * I_;

    float acc[2][5][4];
#pragma unroll
    for (int mi = 0; mi < 2; mi++)
#pragma unroll
        for (int ni = 0; ni < 5; ni++)
#pragma unroll
            for (int q = 0; q < 4; q++) acc[mi][ni][q] = 0.0f;

    // staging coords: one A entry (row am, k-half ah8) and one W entry (t<160)
    const int am  = t >> 1;
    const int ah8 = t & 1;
    float4 xv0, xv1, wv0, wv1;

    // All gmem pointers here are 8B-aligned: route offset r*338*4 == 8 mod 16,
    // row strides XS*4 and I_*4, and kg*4 (kg even) are multiples of 8.
    auto ld8 = [](const float* p, int kg, float4& v0, float4& v1) {
        if (kg + 8 <= I_) {
            float2 a = *reinterpret_cast<const float2*>(p + kg);
            float2 b = *reinterpret_cast<const float2*>(p + kg + 2);
            float2 c = *reinterpret_cast<const float2*>(p + kg + 4);
            float2 d = *reinterpret_cast<const float2*>(p + kg + 6);
            v0 = make_float4(a.x, a.y, b.x, b.y);
            v1 = make_float4(c.x, c.y, d.x, d.y);
        } else {
            float tmp[8];
#pragma unroll
            for (int i = 0; i < 8; i++) tmp[i] = (kg + i < I_) ? p[kg + i] : 0.0f;
            v0 = make_float4(tmp[0], tmp[1], tmp[2], tmp[3]);
            v1 = make_float4(tmp[4], tmp[5], tmp[6], tmp[7]);
        }
    };

    auto load_regs = [&](int s) {
        const int k0 = s * KC;
        ld8(xr + (size_t)am * XS, k0 + ah8 * 8, xv0, xv1);
        if (t < 2 * NH)
            ld8(wr + (size_t)am * I_, k0 + ah8 * 8, wv0, wv1);
    };
    auto cvt_store = [&](int buf) {
        int off = swz(am, ah8);
        sts128(a_hi[buf] + off,
               pack_hi(xv0.x, xv0.y), pack_hi(xv0.z, xv0.w),
               pack_hi(xv1.x, xv1.y), pack_hi(xv1.z, xv1.w));
        sts128(a_lo[buf] + off,
               pack_lo(xv0.x, xv0.y), pack_lo(xv0.z, xv0.w),
               pack_lo(xv1.x, xv1.y), pack_lo(xv1.z, xv1.w));
        if (t < 2 * NH) {
            sts128(b_hi[buf] + off,
                   pack_hi(wv0.x, wv0.y), pack_hi(wv0.z, wv0.w),
                   pack_hi(wv1.x, wv1.y), pack_hi(wv1.z, wv1.w));
            sts128(b_lo[buf] + off,
                   pack_lo(wv0.x, wv0.y), pack_lo(wv0.z, wv0.w),
                   pack_lo(wv1.x, wv1.y), pack_lo(wv1.z, wv1.w));
        }
    };

    // ldsm addressing (swizzle-aware)
    const int a_row = lane & 15;
    const int a_kh  = lane >> 4;
    const int b_row = lane & 7;
    const int b_kh  = (lane >> 3) & 1;
    const int b_ts  = lane >> 4;

    load_regs(0);
    cvt_store(0);
    __syncthreads();

    for (int s = 0; s < NSTAGES; s++) {
        const int cur = s & 1;
        if (s + 1 < NSTAGES) load_regs(s + 1);

        unsigned ah[2][4], al[2][4];
#pragma unroll
        for (int mi = 0; mi < 2; mi++) {
            int row = (wm * 2 + mi) * 16 + a_row;
            ldsm4(ah[mi], sptr(a_hi[cur] + swz(row, a_kh)));
            ldsm4(al[mi], sptr(a_lo[cur] + swz(row, a_kh)));
        }
        unsigned bh[5][2], bl[5][2];
#pragma unroll
        for (int q = 0; q < 2; q++) {
            int row = (wn * 5 + q * 2 + b_ts) * 8 + b_row;
            unsigned d4[4];
            ldsm4(d4, sptr(b_hi[cur] + swz(row, b_kh)));
            bh[q * 2][0] = d4[0]; bh[q * 2][1] = d4[1];
            bh[q * 2 + 1][0] = d4[2]; bh[q * 2 + 1][1] = d4[3];
            ldsm4(d4, sptr(b_lo[cur] + swz(row, b_kh)));
            bl[q * 2][0] = d4[0]; bl[q * 2][1] = d4[1];
            bl[q * 2 + 1][0] = d4[2]; bl[q * 2 + 1][1] = d4[3];
        }
        {
            int row = (wn * 5 + 4) * 8 + b_row;
            ldsm2(bh[4], sptr(b_hi[cur] + swz(row, b_kh)));
            ldsm2(bl[4], sptr(b_lo[cur] + swz(row, b_kh)));
        }
#pragma unroll
        for (int ni = 0; ni < 5; ni++)
#pragma unroll
            for (int mi = 0; mi < 2; mi++)
                mma16816(acc[mi][ni], ah[mi], bh[ni]);
#pragma unroll
        for (int ni = 0; ni < 5; ni++)
#pragma unroll
            for (int mi = 0; mi < 2; mi++)
                mma16816(acc[mi][ni], ah[mi], bl[ni]);
#pragma unroll
        for (int ni = 0; ni < 5; ni++)
#pragma unroll
            for (int mi = 0; mi < 2; mi++)
                mma16816(acc[mi][ni], al[mi], bh[ni]);

        if (s + 1 < NSTAGES) cvt_store((s + 1) & 1);
        __syncthreads();
    }

    float* ur = g_uhat + (size_t)r * N_ + (size_t)nhalf * NH;
    const int crow = lane >> 2;
    const int ccol = (lane & 3) * 2;
#pragma unroll
    for (int mi = 0; mi < 2; mi++) {
        int m0 = (wm * 2 + mi) * 16 + crow;
#pragma unroll
        for (int ni = 0; ni < 5; ni++) {
            int n0 = (wn * 5 + ni) * 8 + ccol;
            *reinterpret_cast<float2*>(&ur[(size_t)m0 * BRS + n0]) =
                make_float2(acc[mi][ni][0], acc[mi][ni][1]);
            *reinterpret_cast<float2*>(&ur[(size_t)(m0 + 8) * BRS + n0]) =
                make_float2(acc[mi][ni][2], acc[mi][ni][3]);
        }
    }
}

// ---------------------------------------------------------------------------
__global__ void softmax_kernel() {
    const int c = blockIdx.x;
    const int t = threadIdx.x;
    __shared__ float red[256];

    float mx = -1e30f;
    for (int r = t; r < R_; r += 256) mx = fmaxf(mx, g_b[r * C_ + c]);
    red[t] = mx; __syncthreads();
    for (int s = 128; s; s >>= 1) {
        if (t < s) red[t] = fmaxf(red[t], red[t + s]);
        __syncthreads();
    }
    mx = red[0]; __syncthreads();

    float sum = 0.0f;
    for (int r = t; r < R_; r += 256) sum += expf(g_b[r * C_ + c] - mx);
    red[t] = sum; __syncthreads();
    for (int s = 128; s; s >>= 1) {
        if (t < s) red[t] += red[t + s];
        __syncthreads();
    }
    float inv = 1.0f / red[0];

    for (int r = t; r < R_; r += 256)
        g_c[r * C_ + c] = expf(g_b[r * C_ + c] - mx) * inv;
}

// ---------------------------------------------------------------------------
// sv1: float4 loads. block (40 n4, 8 b), grid (16 b-groups, NCHUNK chunks).
__global__ __launch_bounds__(320) void sv1_kernel() {
    const int n4 = threadIdx.x;
    const int b  = blockIdx.x * 8 + threadIdx.y;
    const int ch = blockIdx.y;
    const int c  = n4 >> 2;
    const float4* ub = reinterpret_cast<const float4*>(g_uhat + (size_t)b * BRS);
    const int r0 = ch * RCHUNK;

    float4 acc = make_float4(0.f, 0.f, 0.f, 0.f);
#pragma unroll 8
    for (int r = r0; r < r0 + RCHUNK; r++) {
        float cc = g_c[r * C_ + c];
        float4 u = ub[r * 40 + n4];
        acc.x += cc * u.x; acc.y += cc * u.y;
        acc.z += cc * u.z; acc.w += cc * u.w;
    }
    reinterpret_cast<float4*>(g_spart)[((size_t)ch * B_ + b) * 40 + n4] = acc;
}

__global__ __launch_bounds__(160) void sv2_kernel(int write_out, float* __restrict__ out) {
    const int b = blockIdx.x;
    const int n = threadIdx.x;
    float s = 0.0f;
#pragma unroll
    for (int q = 0; q < NCHUNK; q++) s += g_spart[((size_t)q * B_ + b) * N_ + n];
    float v = s * fabsf(s) / (1.0f + s * s);
    g_v[b * N_ + n] = v;
    if (write_out) out[b * N_ + n] = v;
}

// ---------------------------------------------------------------------------
// agree: float4. block (40 n4, 8 b-slices), one block per route.
__global__ __launch_bounds__(320) void agree_kernel() {
    const int r  = blockIdx.x;
    const int n4 = threadIdx.x;
    const int q  = threadIdx.y;
    const int t  = q * 40 + n4;
    const float4* up = reinterpret_cast<const float4*>(g_uhat + (size_t)r * N_);
    const float4* vp = reinterpret_cast<const float4*>(g_v);

    float acc = 0.0f;
#pragma unroll 4
    for (int b = q; b < B_; b += 8) {
        float4 u = up[(size_t)b * (BRS / 4) + n4];
        float4 v = vp[b * 40 + n4];
        acc += u.x * v.x + u.y * v.y + u.z * v.z + u.w * v.w;
    }

    __shared__ float red[320];
    red[t] = acc;
    __syncthreads();
    if (t < 40) {
        float a = 0.0f;
#pragma unroll
        for (int s = 0; s < 8; s++) a += red[s * 40 + t];
        red[t] = a;
    }
    __syncthreads();
    if (t < 10) {
        float a = red[t * 4] + red[t * 4 + 1] + red[t * 4 + 2] + red[t * 4 + 3];
        g_b[r * C_ + t] += a * (1.0f / 128.0f);
    }
}

// ---------------------------------------------------------------------------
extern "C" void kernel_launch(void* const* d_in, const int* in_sizes, int n_in,
                              void* d_out, int out_size) {
    const float* x = (const float*)d_in[0];
    const float* W = (const float*)d_in[1];
    if (n_in >= 2 && in_sizes[0] == R_ * C_ * O_ * I_) {  // defensive order detect
        W = (const float*)d_in[0];
        x = (const float*)d_in[1];
    }
    float* out = (float*)d_out;

    // Launches 0-2: idempotent init; launch index 3 = uhat (ncu capture slot).
    for (int i = 0; i < 3; i++)
        init_kernel<<<(R_ * C_ + 255) / 256, 256>>>();
    uhat_kernel<<<dim3(2, R_), 256>>>(x, W);
    for (int it = 0; it < 3; it++) {
        if (it > 0) softmax_kernel<<<C_, 256>>>();   // iter 0: uniform c from init
        sv1_kernel<<<dim3(16, NCHUNK), dim3(40, 8)>>>();
        sv2_kernel<<<B_, 160>>>(it == 2 ? 1 : 0, out);
        if (it < 2) agree_kernel<<<R_, dim3(40, 8)>>>();
    }
}

// round 14
// speedup vs baseline: 1.3708x; 1.3708x over previous
#include <cuda_runtime.h>
#include <cuda_bf16.h>
#include <math.h>

// Problem dims
#define B_  128
#define R_  1152
#define C_  10
#define O_  16
#define I_  338
#define N_  160
#define BRS (R_*N_)
#define NCHUNK 16
#define RCHUNK (R_/NCHUNK)    // 72

#define AST 24                // row stride in bf16 per k16 subtile (48B)
#define NSTG 11               // k32 stages: 11*32 = 352 >= 338
#define NH 80                 // N per block

// dynamic smem plane layout (bytes): 4 planes per operand/half = (buf*2+sub)
#define APL 6144              // 128*24*2
#define BPL 3840              // 80*24*2
#define OFF_ALO 24576
#define OFF_BHI 49152
#define OFF_BLO 64512
#define SMEM_DYN 79872

// Scratch
__device__ float g_uhat[(size_t)B_ * R_ * N_];
__device__ float g_b[R_ * C_];
__device__ float g_c[R_ * C_];
__device__ float g_v[B_ * N_];
__device__ float g_spart[NCHUNK * B_ * N_];

// ---------------------------------------------------------------------------
__device__ __forceinline__ unsigned sptr(const void* p) {
    return (unsigned)__cvta_generic_to_shared(p);
}
__device__ __forceinline__ void ldsm4(unsigned* d, unsigned a) {
    asm volatile("ldmatrix.sync.aligned.m8n8.x4.shared.b16 {%0,%1,%2,%3}, [%4];"
                 : "=r"(d[0]), "=r"(d[1]), "=r"(d[2]), "=r"(d[3]) : "r"(a));
}
__device__ __forceinline__ void ldsm2(unsigned* d, unsigned a) {
    asm volatile("ldmatrix.sync.aligned.m8n8.x2.shared.b16 {%0,%1}, [%2];"
                 : "=r"(d[0]), "=r"(d[1]) : "r"(a));
}
__device__ __forceinline__ void mma16816(float* c, const unsigned* a, const unsigned* b) {
    asm volatile(
        "mma.sync.aligned.m16n8k16.row.col.f32.bf16.bf16.f32 "
        "{%0,%1,%2,%3}, {%4,%5,%6,%7}, {%8,%9}, {%0,%1,%2,%3};"
        : "+f"(c[0]), "+f"(c[1]), "+f"(c[2]), "+f"(c[3])
        : "r"(a[0]), "r"(a[1]), "r"(a[2]), "r"(a[3]), "r"(b[0]), "r"(b[1]));
}

// ---------------------------------------------------------------------------
__global__ void init_kernel() {
    int i = blockIdx.x * blockDim.x + threadIdx.x;
    if (i < R_ * C_) {
        g_b[i] = 0.0f;
        g_c[i] = 1.0f / (float)R_;   // softmax of zero logits over routes
    }
}

// ---------------------------------------------------------------------------
// u_hat via bf16 hi/lo split HMMA. Round-9 geometry per k16 subtile,
// two subtiles per barrier (syncs 22 -> 11), fine-grain load/mma interleave.
// grid (2, R_): both nhalf CTAs of a route co-resident -> x L2 reuse.
__global__ __launch_bounds__(256, 2) void uhat_kernel(const float* __restrict__ x,
                                                      const float* __restrict__ W) {
    extern __shared__ char sm[];
    const int nhalf = blockIdx.x;
    const int r     = blockIdx.y;
    const int t     = threadIdx.x;
    const int warp  = t >> 5;
    const int lane  = t & 31;
    const int wm    = warp >> 1;
    const int wn    = warp & 1;

    const float* xr = x + (size_t)r * I_;
    const float* wr = W + (size_t)r * N_ * I_ + (size_t)nhalf * NH * I_;

    float acc[2][5][4];
#pragma unroll
    for (int mi = 0; mi < 2; mi++)
#pragma unroll
        for (int ni = 0; ni < 5; ni++)
#pragma unroll
            for (int q = 0; q < 4; q++) acc[mi][ni][q] = 0.0f;

    const int a_row_in = lane & 15;
    const int a_kgrp   = (lane >> 4) * 8;
    const int b_row_in = lane & 7;
    const int b_kgrp   = ((lane >> 3) & 1) * 8;
    const int b_tsel   = lane >> 4;

    float2 xa[4], wb[3];

    // plane accessors: p = buf*2 + sub
    auto aHi = [&](int p) { return (__nv_bfloat16*)(sm + p * APL); };
    auto aLo = [&](int p) { return (__nv_bfloat16*)(sm + OFF_ALO + p * APL); };
    auto bHi = [&](int p) { return (__nv_bfloat16*)(sm + OFF_BHI + p * BPL); };
    auto bLo = [&](int p) { return (__nv_bfloat16*)(sm + OFF_BLO + p * BPL); };

    // ---- round-9 per-k16 load: A 4x float2, W 3x float2 (coalesced) ----
    auto load_sub = [&](int s, int sub) {
        const int k0 = s * 32 + sub * 16;
#pragma unroll
        for (int j = 0; j < 4; j++) {
            int e = t + j * 256;
            int m = e >> 3, k = (e & 7) * 2, kg = k0 + k;
            xa[j] = (kg < I_) ? *reinterpret_cast<const float2*>(
                                    xr + (size_t)m * ((size_t)R_ * I_) + kg)
                              : make_float2(0.0f, 0.0f);
        }
#pragma unroll
        for (int j = 0; j < 3; j++) {
            int e = t + j * 256;
            int n = e >> 3, k = (e & 7) * 2, kg = k0 + k;
            wb[j] = (e < NH * 8 && kg < I_)
                        ? *reinterpret_cast<const float2*>(wr + (size_t)n * I_ + kg)
                        : make_float2(0.0f, 0.0f);
        }
    };
    auto cvt_store_sub = [&](int p) {
#pragma unroll
        for (int j = 0; j < 4; j++) {
            int e = t + j * 256;
            int m = e >> 3, k = (e & 7) * 2;
            __nv_bfloat16 h0 = __float2bfloat16(xa[j].x), h1 = __float2bfloat16(xa[j].y);
            __nv_bfloat16 l0 = __float2bfloat16(xa[j].x - __bfloat162float(h0));
            __nv_bfloat16 l1 = __float2bfloat16(xa[j].y - __bfloat162float(h1));
            *reinterpret_cast<__nv_bfloat162*>(&aHi(p)[m * AST + k]) = __halves2bfloat162(h0, h1);
            *reinterpret_cast<__nv_bfloat162*>(&aLo(p)[m * AST + k]) = __halves2bfloat162(l0, l1);
        }
#pragma unroll
        for (int j = 0; j < 3; j++) {
            int e = t + j * 256;
            if (e < NH * 8) {
                int n = e >> 3, k = (e & 7) * 2;
                __nv_bfloat16 h0 = __float2bfloat16(wb[j].x), h1 = __float2bfloat16(wb[j].y);
                __nv_bfloat16 l0 = __float2bfloat16(wb[j].x - __bfloat162float(h0));
                __nv_bfloat16 l1 = __float2bfloat16(wb[j].y - __bfloat162float(h1));
                *reinterpret_cast<__nv_bfloat162*>(&bHi(p)[n * AST + k]) = __halves2bfloat162(h0, h1);
                *reinterpret_cast<__nv_bfloat162*>(&bLo(p)[n * AST + k]) = __halves2bfloat162(l0, l1);
            }
        }
    };
    auto mma_sub = [&](int p) {
        unsigned ah[2][4], al[2][4];
#pragma unroll
        for (int mi = 0; mi < 2; mi++) {
            int row = (wm * 2 + mi) * 16 + a_row_in;
            ldsm4(ah[mi], sptr(&aHi(p)[row * AST + a_kgrp]));
            ldsm4(al[mi], sptr(&aLo(p)[row * AST + a_kgrp]));
        }
        unsigned bh[5][2], bl[5][2];
#pragma unroll
        for (int q = 0; q < 2; q++) {
            int row = (wn * 5 + q * 2 + b_tsel) * 8 + b_row_in;
            unsigned d4[4];
            ldsm4(d4, sptr(&bHi(p)[row * AST + b_kgrp]));
            bh[q * 2][0] = d4[0]; bh[q * 2][1] = d4[1];
            bh[q * 2 + 1][0] = d4[2]; bh[q * 2 + 1][1] = d4[3];
            ldsm4(d4, sptr(&bLo(p)[row * AST + b_kgrp]));
            bl[q * 2][0] = d4[0]; bl[q * 2][1] = d4[1];
            bl[q * 2 + 1][0] = d4[2]; bl[q * 2 + 1][1] = d4[3];
        }
        {
            int row = (wn * 5 + 4) * 8 + b_row_in;
            ldsm2(bh[4], sptr(&bHi(p)[row * AST + b_kgrp]));
            ldsm2(bl[4], sptr(&bLo(p)[row * AST + b_kgrp]));
        }
#pragma unroll
        for (int ni = 0; ni < 5; ni++)
#pragma unroll
            for (int mi = 0; mi < 2; mi++)
                mma16816(acc[mi][ni], ah[mi], bh[ni]);
#pragma unroll
        for (int ni = 0; ni < 5; ni++)
#pragma unroll
            for (int mi = 0; mi < 2; mi++)
                mma16816(acc[mi][ni], ah[mi], bl[ni]);
#pragma unroll
        for (int ni = 0; ni < 5; ni++)
#pragma unroll
            for (int mi = 0; mi < 2; mi++)
                mma16816(acc[mi][ni], al[mi], bh[ni]);
    };

    // prologue: fill buffer 0, both subtiles
    load_sub(0, 0); cvt_store_sub(0);
    load_sub(0, 1); cvt_store_sub(1);
    __syncthreads();

    for (int s = 0; s < NSTG; s++) {
        const int cur = s & 1;
        const int nxt = cur ^ 1;
        const bool more = (s + 1 < NSTG);

        if (more) load_sub(s + 1, 0);
        mma_sub(cur * 2 + 0);
        if (more) { cvt_store_sub(nxt * 2 + 0); load_sub(s + 1, 1); }
        mma_sub(cur * 2 + 1);
        if (more) cvt_store_sub(nxt * 2 + 1);
        __syncthreads();
    }

    float* ur = g_uhat + (size_t)r * N_ + (size_t)nhalf * NH;
    const int crow = lane >> 2;
    const int ccol = (lane & 3) * 2;
#pragma unroll
    for (int mi = 0; mi < 2; mi++) {
        int m0 = (wm * 2 + mi) * 16 + crow;
#pragma unroll
        for (int ni = 0; ni < 5; ni++) {
            int n0 = (wn * 5 + ni) * 8 + ccol;
            *reinterpret_cast<float2*>(&ur[(size_t)m0 * BRS + n0]) =
                make_float2(acc[mi][ni][0], acc[mi][ni][1]);
            *reinterpret_cast<float2*>(&ur[(size_t)(m0 + 8) * BRS + n0]) =
                make_float2(acc[mi][ni][2], acc[mi][ni][3]);
        }
    }
}

// ---------------------------------------------------------------------------
__global__ void softmax_kernel() {
    const int c = blockIdx.x;
    const int t = threadIdx.x;
    __shared__ float red[256];

    float mx = -1e30f;
    for (int r = t; r < R_; r += 256) mx = fmaxf(mx, g_b[r * C_ + c]);
    red[t] = mx; __syncthreads();
    for (int s = 128; s; s >>= 1) {
        if (t < s) red[t] = fmaxf(red[t], red[t + s]);
        __syncthreads();
    }
    mx = red[0]; __syncthreads();

    float sum = 0.0f;
    for (int r = t; r < R_; r += 256) sum += expf(g_b[r * C_ + c] - mx);
    red[t] = sum; __syncthreads();
    for (int s = 128; s; s >>= 1) {
        if (t < s) red[t] += red[t + s];
        __syncthreads();
    }
    float inv = 1.0f / red[0];

    for (int r = t; r < R_; r += 256)
        g_c[r * C_ + c] = expf(g_b[r * C_ + c] - mx) * inv;
}

// ---------------------------------------------------------------------------
// sv1: float4 loads. block (40 n4, 8 b), grid (16 b-groups, NCHUNK chunks).
__global__ __launch_bounds__(320) void sv1_kernel() {
    const int n4 = threadIdx.x;
    const int b  = blockIdx.x * 8 + threadIdx.y;
    const int ch = blockIdx.y;
    const int c  = n4 >> 2;
    const float4* ub = reinterpret_cast<const float4*>(g_uhat + (size_t)b * BRS);
    const int r0 = ch * RCHUNK;

    float4 acc = make_float4(0.f, 0.f, 0.f, 0.f);
#pragma unroll 8
    for (int r = r0; r < r0 + RCHUNK; r++) {
        float cc = g_c[r * C_ + c];
        float4 u = ub[r * 40 + n4];
        acc.x += cc * u.x; acc.y += cc * u.y;
        acc.z += cc * u.z; acc.w += cc * u.w;
    }
    reinterpret_cast<float4*>(g_spart)[((size_t)ch * B_ + b) * 40 + n4] = acc;
}

__global__ __launch_bounds__(160) void sv2_kernel(int write_out, float* __restrict__ out) {
    const int b = blockIdx.x;
    const int n = threadIdx.x;
    float s = 0.0f;
#pragma unroll
    for (int q = 0; q < NCHUNK; q++) s += g_spart[((size_t)q * B_ + b) * N_ + n];
    float v = s * fabsf(s) / (1.0f + s * s);
    g_v[b * N_ + n] = v;
    if (write_out) out[b * N_ + n] = v;
}

// ---------------------------------------------------------------------------
// agree: float4. block (40 n4, 8 b-slices), one block per route.
__global__ __launch_bounds__(320) void agree_kernel() {
    const int r  = blockIdx.x;
    const int n4 = threadIdx.x;
    const int q  = threadIdx.y;
    const int t  = q * 40 + n4;
    const float4* up = reinterpret_cast<const float4*>(g_uhat + (size_t)r * N_);
    const float4* vp = reinterpret_cast<const float4*>(g_v);

    float acc = 0.0f;
#pragma unroll 4
    for (int b = q; b < B_; b += 8) {
        float4 u = up[(size_t)b * (BRS / 4) + n4];
        float4 v = vp[b * 40 + n4];
        acc += u.x * v.x + u.y * v.y + u.z * v.z + u.w * v.w;
    }

    __shared__ float red[320];
    red[t] = acc;
    __syncthreads();
    if (t < 40) {
        float a = 0.0f;
#pragma unroll
        for (int s = 0; s < 8; s++) a += red[s * 40 + t];
        red[t] = a;
    }
    __syncthreads();
    if (t < 10) {
        float a = red[t * 4] + red[t * 4 + 1] + red[t * 4 + 2] + red[t * 4 + 3];
        g_b[r * C_ + t] += a * (1.0f / 128.0f);
    }
}

// ---------------------------------------------------------------------------
extern "C" void kernel_launch(void* const* d_in, const int* in_sizes, int n_in,
                              void* d_out, int out_size) {
    const float* x = (const float*)d_in[0];
    const float* W = (const float*)d_in[1];
    if (n_in >= 2 && in_sizes[0] == R_ * C_ * O_ * I_) {  // defensive order detect
        W = (const float*)d_in[0];
        x = (const float*)d_in[1];
    }
    float* out = (float*)d_out;

    cudaFuncSetAttribute(uhat_kernel,
                         cudaFuncAttributeMaxDynamicSharedMemorySize, SMEM_DYN);

    // Launches 0-2: idempotent init; launch index 3 = uhat (ncu capture slot).
    for (int i = 0; i < 3; i++)
        init_kernel<<<(R_ * C_ + 255) / 256, 256>>>();
    uhat_kernel<<<dim3(2, R_), 256, SMEM_DYN>>>(x, W);
    for (int it = 0; it < 3; it++) {
        if (it > 0) softmax_kernel<<<C_, 256>>>();   // iter 0: uniform c from init
        sv1_kernel<<<dim3(16, NCHUNK), dim3(40, 8)>>>();
        sv2_kernel<<<B_, 160>>>(it == 2 ? 1 : 0, out);
        if (it < 2) agree_kernel<<<R_, dim3(40, 8)>>>();
    }
}

// round 16
// speedup vs baseline: 1.3726x; 1.0013x over previous
#include <cuda_runtime.h>
#include <cuda_bf16.h>
#include <math.h>

// Problem dims
#define B_  128
#define R_  1152
#define C_  10
#define O_  16
#define I_  338
#define N_  160
#define BRS (R_*N_)
#define NCHUNK 16
#define RCHUNK (R_/NCHUNK)    // 72

#define AST 24                // row stride in bf16 per k16 subtile (48B)
#define NSTG 11               // k32 stages: 11*32 = 352 >= 338
#define NH 80                 // N per block

// dynamic smem plane layout (bytes): 4 planes per operand/half = (buf*2+sub)
#define APL 6144              // 128*24*2
#define BPL 3840              // 80*24*2
#define OFF_ALO 24576
#define OFF_BHI 49152
#define OFF_BLO 64512
#define SMEM_DYN 79872

// Scratch
__device__ float g_uhat[(size_t)B_ * R_ * N_];
__device__ float g_b[R_ * C_];
__device__ float g_c[R_ * C_];
__device__ float g_v[B_ * N_];
__device__ float g_spart[NCHUNK * B_ * N_];

// ---------------------------------------------------------------------------
__device__ __forceinline__ unsigned sptr(const void* p) {
    return (unsigned)__cvta_generic_to_shared(p);
}
__device__ __forceinline__ void ldsm4(unsigned* d, unsigned a) {
    asm volatile("ldmatrix.sync.aligned.m8n8.x4.shared.b16 {%0,%1,%2,%3}, [%4];"
                 : "=r"(d[0]), "=r"(d[1]), "=r"(d[2]), "=r"(d[3]) : "r"(a));
}
__device__ __forceinline__ void ldsm2(unsigned* d, unsigned a) {
    asm volatile("ldmatrix.sync.aligned.m8n8.x2.shared.b16 {%0,%1}, [%2];"
                 : "=r"(d[0]), "=r"(d[1]) : "r"(a));
}
__device__ __forceinline__ void mma16816(float* c, const unsigned* a, const unsigned* b) {
    asm volatile(
        "mma.sync.aligned.m16n8k16.row.col.f32.bf16.bf16.f32 "
        "{%0,%1,%2,%3}, {%4,%5,%6,%7}, {%8,%9}, {%0,%1,%2,%3};"
        : "+f"(c[0]), "+f"(c[1]), "+f"(c[2]), "+f"(c[3])
        : "r"(a[0]), "r"(a[1]), "r"(a[2]), "r"(a[3]), "r"(b[0]), "r"(b[1]));
}

// ---------------------------------------------------------------------------
__global__ void init_kernel() {
    int i = blockIdx.x * blockDim.x + threadIdx.x;
    if (i < R_ * C_) {
        g_b[i] = 0.0f;
        g_c[i] = 1.0f / (float)R_;   // softmax of zero logits over routes
    }
}

// ---------------------------------------------------------------------------
// u_hat via bf16 hi/lo split HMMA. Round-9 staging geometry per k16 subtile,
// two subtiles per barrier (syncs 22 -> 11), fine-grain load/mma interleave.
// grid (2, R_): both nhalf CTAs of a route co-resident -> x L2 reuse.
__global__ __launch_bounds__(256, 2) void uhat_kernel(const float* __restrict__ x,
                                                      const float* __restrict__ W) {
    extern __shared__ char sm[];
    const int nhalf = blockIdx.x;
    const int r     = blockIdx.y;
    const int t     = threadIdx.x;
    const int warp  = t >> 5;
    const int lane  = t & 31;
    const int wm    = warp >> 1;
    const int wn    = warp & 1;

    const float* xr = x + (size_t)r * I_;
    const float* wr = W + (size_t)r * N_ * I_ + (size_t)nhalf * NH * I_;

    float acc[2][5][4];
#pragma unroll
    for (int mi = 0; mi < 2; mi++)
#pragma unroll
        for (int ni = 0; ni < 5; ni++)
#pragma unroll
            for (int q = 0; q < 4; q++) acc[mi][ni][q] = 0.0f;

    const int a_row_in = lane & 15;
    const int a_kgrp   = (lane >> 4) * 8;
    const int b_row_in = lane & 7;
    const int b_kgrp   = ((lane >> 3) & 1) * 8;
    const int b_tsel   = lane >> 4;

    float2 xa[4], wb[3];

    // plane accessors: p = buf*2 + sub
    auto aHi = [&](int p) { return (__nv_bfloat16*)(sm + p * APL); };
    auto aLo = [&](int p) { return (__nv_bfloat16*)(sm + OFF_ALO + p * APL); };
    auto bHi = [&](int p) { return (__nv_bfloat16*)(sm + OFF_BHI + p * BPL); };
    auto bLo = [&](int p) { return (__nv_bfloat16*)(sm + OFF_BLO + p * BPL); };

    auto load_sub = [&](int s, int sub) {
        const int k0 = s * 32 + sub * 16;
#pragma unroll
        for (int j = 0; j < 4; j++) {
            int e = t + j * 256;
            int m = e >> 3, k = (e & 7) * 2, kg = k0 + k;
            xa[j] = (kg < I_) ? *reinterpret_cast<const float2*>(
                                    xr + (size_t)m * ((size_t)R_ * I_) + kg)
                              : make_float2(0.0f, 0.0f);
        }
#pragma unroll
        for (int j = 0; j < 3; j++) {
            int e = t + j * 256;
            int n = e >> 3, k = (e & 7) * 2, kg = k0 + k;
            wb[j] = (e < NH * 8 && kg < I_)
                        ? *reinterpret_cast<const float2*>(wr + (size_t)n * I_ + kg)
                        : make_float2(0.0f, 0.0f);
        }
    };
    auto cvt_store_sub = [&](int p) {
#pragma unroll
        for (int j = 0; j < 4; j++) {
            int e = t + j * 256;
            int m = e >> 3, k = (e & 7) * 2;
            __nv_bfloat16 h0 = __float2bfloat16(xa[j].x), h1 = __float2bfloat16(xa[j].y);
            __nv_bfloat16 l0 = __float2bfloat16(xa[j].x - __bfloat162float(h0));
            __nv_bfloat16 l1 = __float2bfloat16(xa[j].y - __bfloat162float(h1));
            *reinterpret_cast<__nv_bfloat162*>(&aHi(p)[m * AST + k]) = __halves2bfloat162(h0, h1);
            *reinterpret_cast<__nv_bfloat162*>(&aLo(p)[m * AST + k]) = __halves2bfloat162(l0, l1);
        }
#pragma unroll
        for (int j = 0; j < 3; j++) {
            int e = t + j * 256;
            if (e < NH * 8) {
                int n = e >> 3, k = (e & 7) * 2;
                __nv_bfloat16 h0 = __float2bfloat16(wb[j].x), h1 = __float2bfloat16(wb[j].y);
                __nv_bfloat16 l0 = __float2bfloat16(wb[j].x - __bfloat162float(h0));
                __nv_bfloat16 l1 = __float2bfloat16(wb[j].y - __bfloat162float(h1));
                *reinterpret_cast<__nv_bfloat162*>(&bHi(p)[n * AST + k]) = __halves2bfloat162(h0, h1);
                *reinterpret_cast<__nv_bfloat162*>(&bLo(p)[n * AST + k]) = __halves2bfloat162(l0, l1);
            }
        }
    };
    auto mma_sub = [&](int p) {
        unsigned ah[2][4], al[2][4];
#pragma unroll
        for (int mi = 0; mi < 2; mi++) {
            int row = (wm * 2 + mi) * 16 + a_row_in;
            ldsm4(ah[mi], sptr(&aHi(p)[row * AST + a_kgrp]));
            ldsm4(al[mi], sptr(&aLo(p)[row * AST + a_kgrp]));
        }
        unsigned bh[5][2], bl[5][2];
#pragma unroll
        for (int q = 0; q < 2; q++) {
            int row = (wn * 5 + q * 2 + b_tsel) * 8 + b_row_in;
            unsigned d4[4];
            ldsm4(d4, sptr(&bHi(p)[row * AST + b_kgrp]));
            bh[q * 2][0] = d4[0]; bh[q * 2][1] = d4[1];
            bh[q * 2 + 1][0] = d4[2]; bh[q * 2 + 1][1] = d4[3];
            ldsm4(d4, sptr(&bLo(p)[row * AST + b_kgrp]));
            bl[q * 2][0] = d4[0]; bl[q * 2][1] = d4[1];
            bl[q * 2 + 1][0] = d4[2]; bl[q * 2 + 1][1] = d4[3];
        }
        {
            int row = (wn * 5 + 4) * 8 + b_row_in;
            ldsm2(bh[4], sptr(&bHi(p)[row * AST + b_kgrp]));
            ldsm2(bl[4], sptr(&bLo(p)[row * AST + b_kgrp]));
        }
#pragma unroll
        for (int ni = 0; ni < 5; ni++)
#pragma unroll
            for (int mi = 0; mi < 2; mi++)
                mma16816(acc[mi][ni], ah[mi], bh[ni]);
#pragma unroll
        for (int ni = 0; ni < 5; ni++)
#pragma unroll
            for (int mi = 0; mi < 2; mi++)
                mma16816(acc[mi][ni], ah[mi], bl[ni]);
#pragma unroll
        for (int ni = 0; ni < 5; ni++)
#pragma unroll
            for (int mi = 0; mi < 2; mi++)
                mma16816(acc[mi][ni], al[mi], bh[ni]);
    };

    // prologue: fill buffer 0, both subtiles
    load_sub(0, 0); cvt_store_sub(0);
    load_sub(0, 1); cvt_store_sub(1);
    __syncthreads();

    for (int s = 0; s < NSTG; s++) {
        const int cur = s & 1;
        const int nxt = cur ^ 1;
        const bool more = (s + 1 < NSTG);

        if (more) load_sub(s + 1, 0);
        mma_sub(cur * 2 + 0);
        if (more) { cvt_store_sub(nxt * 2 + 0); load_sub(s + 1, 1); }
        mma_sub(cur * 2 + 1);
        if (more) cvt_store_sub(nxt * 2 + 1);
        __syncthreads();
    }

    float* ur = g_uhat + (size_t)r * N_ + (size_t)nhalf * NH;
    const int crow = lane >> 2;
    const int ccol = (lane & 3) * 2;
#pragma unroll
    for (int mi = 0; mi < 2; mi++) {
        int m0 = (wm * 2 + mi) * 16 + crow;
#pragma unroll
        for (int ni = 0; ni < 5; ni++) {
            int n0 = (wn * 5 + ni) * 8 + ccol;
            *reinterpret_cast<float2*>(&ur[(size_t)m0 * BRS + n0]) =
                make_float2(acc[mi][ni][0], acc[mi][ni][1]);
            *reinterpret_cast<float2*>(&ur[(size_t)(m0 + 8) * BRS + n0]) =
                make_float2(acc[mi][ni][2], acc[mi][ni][3]);
        }
    }
}

// ---------------------------------------------------------------------------
__global__ void softmax_kernel() {
    const int c = blockIdx.x;
    const int t = threadIdx.x;
    __shared__ float red[256];

    float mx = -1e30f;
    for (int r = t; r < R_; r += 256) mx = fmaxf(mx, g_b[r * C_ + c]);
    red[t] = mx; __syncthreads();
    for (int s = 128; s; s >>= 1) {
        if (t < s) red[t] = fmaxf(red[t], red[t + s]);
        __syncthreads();
    }
    mx = red[0]; __syncthreads();

    float sum = 0.0f;
    for (int r = t; r < R_; r += 256) sum += expf(g_b[r * C_ + c] - mx);
    red[t] = sum; __syncthreads();
    for (int s = 128; s; s >>= 1) {
        if (t < s) red[t] += red[t + s];
        __syncthreads();
    }
    float inv = 1.0f / red[0];

    for (int r = t; r < R_; r += 256)
        g_c[r * C_ + c] = expf(g_b[r * C_ + c] - mx) * inv;
}

// ---------------------------------------------------------------------------
// sv1: float4 loads. block (40 n4, 8 b), grid (16 b-groups, NCHUNK chunks).
__global__ __launch_bounds__(320) void sv1_kernel() {
    const int n4 = threadIdx.x;
    const int b  = blockIdx.x * 8 + threadIdx.y;
    const int ch = blockIdx.y;
    const int c  = n4 >> 2;
    const float4* ub = reinterpret_cast<const float4*>(g_uhat + (size_t)b * BRS);
    const int r0 = ch * RCHUNK;

    float4 acc = make_float4(0.f, 0.f, 0.f, 0.f);
#pragma unroll 8
    for (int r = r0; r < r0 + RCHUNK; r++) {
        float cc = g_c[r * C_ + c];
        float4 u = ub[r * 40 + n4];
        acc.x += cc * u.x; acc.y += cc * u.y;
        acc.z += cc * u.z; acc.w += cc * u.w;
    }
    reinterpret_cast<float4*>(g_spart)[((size_t)ch * B_ + b) * 40 + n4] = acc;
}

__global__ __launch_bounds__(160) void sv2_kernel(int write_out, float* __restrict__ out) {
    const int b = blockIdx.x;
    const int n = threadIdx.x;
    float s = 0.0f;
#pragma unroll
    for (int q = 0; q < NCHUNK; q++) s += g_spart[((size_t)q * B_ + b) * N_ + n];
    float v = s * fabsf(s) / (1.0f + s * s);
    g_v[b * N_ + n] = v;
    if (write_out) out[b * N_ + n] = v;
}

// ---------------------------------------------------------------------------
// agree: float4. block (40 n4, 8 b-slices), one block per route.
__global__ __launch_bounds__(320) void agree_kernel() {
    const int r  = blockIdx.x;
    const int n4 = threadIdx.x;
    const int q  = threadIdx.y;
    const int t  = q * 40 + n4;
    const float4* up = reinterpret_cast<const float4*>(g_uhat + (size_t)r * N_);
    const float4* vp = reinterpret_cast<const float4*>(g_v);

    float acc = 0.0f;
#pragma unroll 4
    for (int b = q; b < B_; b += 8) {
        float4 u = up[(size_t)b * (BRS / 4) + n4];
        float4 v = vp[b * 40 + n4];
        acc += u.x * v.x + u.y * v.y + u.z * v.z + u.w * v.w;
    }

    __shared__ float red[320];
    red[t] = acc;
    __syncthreads();
    if (t < 40) {
        float a = 0.0f;
#pragma unroll
        for (int s = 0; s < 8; s++) a += red[s * 40 + t];
        red[t] = a;
    }
    __syncthreads();
    if (t < 10) {
        float a = red[t * 4] + red[t * 4 + 1] + red[t * 4 + 2] + red[t * 4 + 3];
        g_b[r * C_ + t] += a * (1.0f / 128.0f);
    }
}

// ---------------------------------------------------------------------------
extern "C" void kernel_launch(void* const* d_in, const int* in_sizes, int n_in,
                              void* d_out, int out_size) {
    const float* x = (const float*)d_in[0];
    const float* W = (const float*)d_in[1];
    if (n_in >= 2 && in_sizes[0] == R_ * C_ * O_ * I_) {  // defensive order detect
        W = (const float*)d_in[0];
        x = (const float*)d_in[1];
    }
    float* out = (float*)d_out;

    cudaFuncSetAttribute(uhat_kernel,
                         cudaFuncAttributeMaxDynamicSharedMemorySize, SMEM_DYN);

    init_kernel<<<(R_ * C_ + 255) / 256, 256>>>();
    uhat_kernel<<<dim3(2, R_), 256, SMEM_DYN>>>(x, W);
    for (int it = 0; it < 3; it++) {
        if (it > 0) softmax_kernel<<<C_, 256>>>();   // iter 0: uniform c from init
        sv1_kernel<<<dim3(16, NCHUNK), dim3(40, 8)>>>();
        sv2_kernel<<<B_, 160>>>(it == 2 ? 1 : 0, out);
        if (it < 2) agree_kernel<<<R_, dim3(40, 8)>>>();
    }
}